// round 1
// baseline (speedup 1.0000x reference)
#include <cuda_runtime.h>

// Problem constants (fixed by the dataset)
#define B_   128
#define E_   100000
#define F_   5000
#define C_   8
#define DIN_ 10
#define DOUT_ 10
#define H_   (F_ * C_)
#define EPS_ 1e-5f

// ---------------------------------------------------------------------------
// Kernel 1: out[b, e] = x[b, e] + b3[e]   (residual base + output bias)
// Vectorized float4; E % 4 == 0.
// ---------------------------------------------------------------------------
__global__ void init_out_kernel(const float* __restrict__ x,
                                const float* __restrict__ b3,
                                float* __restrict__ out) {
    const int E4 = E_ / 4;
    int b = blockIdx.y;
    int i = blockIdx.x * blockDim.x + threadIdx.x;
    if (i >= E4) return;
    const float4* xr  = reinterpret_cast<const float4*>(x) + (size_t)b * E4;
    const float4* b3r = reinterpret_cast<const float4*>(b3);
    float4* outr      = reinterpret_cast<float4*>(out) + (size_t)b * E4;
    float4 xv = xr[i];
    float4 bv = b3r[i];
    float4 o;
    o.x = xv.x + bv.x; o.y = xv.y + bv.y; o.z = xv.z + bv.z; o.w = xv.w + bv.w;
    outr[i] = o;
}

__device__ __forceinline__ float elu1(float z) {
    return z > 0.0f ? z : expm1f(z);
}

// ---------------------------------------------------------------------------
// Kernel 2: one block per function node f, one thread per batch b (128).
//   gather x  -> w1 (10x8)  -> groupLN -> elu(s*h)
//             -> w2 (8x8)   -> groupLN -> elu(h*s)
//             -> w3 (8->10) -> atomicAdd into out
// ---------------------------------------------------------------------------
__global__ __launch_bounds__(B_)
void fn_node_kernel(const float* __restrict__ x,
                    const float* __restrict__ s,
                    const float* __restrict__ w1,
                    const float* __restrict__ b1,
                    const float* __restrict__ w2,
                    const float* __restrict__ b2,
                    const float* __restrict__ w3,
                    const int*   __restrict__ src1,   // in_e[f,d] = src1[(f*10+d)*8]
                    const int*   __restrict__ dst3,   // out_e[f,d] = dst3[(f*10+d)*8]
                    const float* __restrict__ g1,
                    const float* __restrict__ bt1,
                    const float* __restrict__ g2,
                    const float* __restrict__ bt2,
                    float* __restrict__ out) {
    __shared__ float w1s[DIN_ * C_];    // 80
    __shared__ float w2s[C_ * C_];      // 64
    __shared__ float w3s[DOUT_ * C_];   // 80
    __shared__ int   ine[DIN_];
    __shared__ int   oute[DOUT_];
    __shared__ float b1s[C_], b2s[C_], g1s[C_], bt1s[C_], g2s[C_], bt2s[C_];

    const int f   = blockIdx.x;
    const int tid = threadIdx.x;   // == batch index b

    // ---- cooperative parameter load ----
    if (tid < DIN_ * C_)  w1s[tid] = w1[f * (DIN_ * C_) + tid];
    if (tid < C_ * C_)    w2s[tid] = w2[f * (C_ * C_) + tid];
    if (tid < DOUT_ * C_) w3s[tid] = w3[f * (DOUT_ * C_) + tid];
    if (tid < DIN_)       ine[tid]  = src1[(f * DIN_ + tid) * C_];
    if (tid < DOUT_)      oute[tid] = dst3[(f * DOUT_ + tid) * C_];
    if (tid < C_) {
        int hc = f * C_ + tid;
        b1s[tid]  = b1[hc];
        b2s[tid]  = b2[hc];
        g1s[tid]  = g1[hc];
        bt1s[tid] = bt1[hc];
        g2s[tid]  = g2[hc];
        bt2s[tid] = bt2[hc];
    }
    __syncthreads();

    const int b = tid;
    const float* xrow = x + (size_t)b * E_;

    // ---- gather (10 independent L2 loads, MLP=10) ----
    float xv[DIN_];
#pragma unroll
    for (int d = 0; d < DIN_; d++) xv[d] = __ldg(xrow + ine[d]);

    // ---- w1: 10x8 dense ----
    float h[C_];
#pragma unroll
    for (int c = 0; c < C_; c++) {
        float acc = b1s[c];
#pragma unroll
        for (int d = 0; d < DIN_; d++) acc = fmaf(xv[d], w1s[d * C_ + c], acc);
        h[c] = acc;
    }

    // ---- load s[b, f*8 .. f*8+7] (32B aligned sector) ----
    const float4* srow = reinterpret_cast<const float4*>(s + (size_t)b * H_ + f * C_);
    float4 sa = srow[0], sb = srow[1];
    float sv[C_] = {sa.x, sa.y, sa.z, sa.w, sb.x, sb.y, sb.z, sb.w};

    // ---- groupLN 1 (over 8 channels) + affine + elu(s*h) ----
    {
        float sum = 0.f, sq = 0.f;
#pragma unroll
        for (int c = 0; c < C_; c++) { sum += h[c]; sq += h[c] * h[c]; }
        float mu  = sum * 0.125f;
        float var = sq * 0.125f - mu * mu;
        float inv = rsqrtf(var + EPS_);
#pragma unroll
        for (int c = 0; c < C_; c++) {
            float z = (g1s[c] * ((h[c] - mu) * inv) + bt1s[c]) * sv[c];
            h[c] = elu1(z);
        }
    }

    // ---- w2: 8x8 dense block ----
    float h2[C_];
#pragma unroll
    for (int c2 = 0; c2 < C_; c2++) {
        float acc = b2s[c2];
#pragma unroll
        for (int c = 0; c < C_; c++) acc = fmaf(h[c], w2s[c * C_ + c2], acc);
        h2[c2] = acc;
    }

    // ---- groupLN 2 + affine + elu(h*s) ----
    {
        float sum = 0.f, sq = 0.f;
#pragma unroll
        for (int c = 0; c < C_; c++) { sum += h2[c]; sq += h2[c] * h2[c]; }
        float mu  = sum * 0.125f;
        float var = sq * 0.125f - mu * mu;
        float inv = rsqrtf(var + EPS_);
#pragma unroll
        for (int c = 0; c < C_; c++) {
            float z = (g2s[c] * ((h2[c] - mu) * inv) + bt2s[c]) * sv[c];
            h[c] = elu1(z);
        }
    }

    // ---- w3: 8 -> 10 scatter with atomics ----
    float* orow = out + (size_t)b * E_;
#pragma unroll
    for (int d = 0; d < DOUT_; d++) {
        float acc = 0.f;
#pragma unroll
        for (int c = 0; c < C_; c++) acc = fmaf(h[c], w3s[d * C_ + c], acc);
        atomicAdd(orow + oute[d], acc);
    }
}

// ---------------------------------------------------------------------------
// Launch
// ---------------------------------------------------------------------------
extern "C" void kernel_launch(void* const* d_in, const int* in_sizes, int n_in,
                              void* d_out, int out_size) {
    const float* x   = (const float*)d_in[0];
    const float* s   = (const float*)d_in[1];
    const float* w1  = (const float*)d_in[2];
    const float* b1  = (const float*)d_in[3];
    const float* w2  = (const float*)d_in[4];
    const float* b2  = (const float*)d_in[5];
    const float* w3  = (const float*)d_in[6];
    const float* b3  = (const float*)d_in[7];
    const float* g1  = (const float*)d_in[8];
    const float* bt1 = (const float*)d_in[9];
    const float* g2  = (const float*)d_in[10];
    const float* bt2 = (const float*)d_in[11];
    const int*   src1 = (const int*)d_in[12];
    // d_in[13] dst1, d_in[14] src2, d_in[15] dst2, d_in[16] src3 — implied by structure
    const int*   dst3 = (const int*)d_in[17];
    float* out = (float*)d_out;

    // Kernel 1: residual base + b3
    {
        const int E4 = E_ / 4;
        dim3 grid((E4 + 255) / 256, B_);
        init_out_kernel<<<grid, 256>>>(x, b3, out);
    }
    // Kernel 2: per-function-node fused block
    {
        fn_node_kernel<<<F_, B_>>>(x, s, w1, b1, w2, b2, w3,
                                   src1, dst3, g1, bt1, g2, bt2, out);
    }
}

// round 2
// speedup vs baseline: 1.2280x; 1.2280x over previous
#include <cuda_runtime.h>

// Problem constants (fixed by the dataset)
#define B_   128
#define E_   100000
#define F_   5000
#define C_   8
#define DIN_ 10
#define DOUT_ 10
#define H_   (F_ * C_)
#define EPS_ 1e-5f

// Transposed scratch: batch-contiguous layouts (51.2 MB each, static device mem)
__device__ float g_xT[(size_t)E_ * B_];    // xT[e][b]
__device__ float g_outT[(size_t)E_ * B_];  // outT[e][b] = x + b3, then scatter target

// ---------------------------------------------------------------------------
// Kernel A: tiled transpose x[b][e] -> xT[e][b], and outT[e][b] = x + b3[e]
// grid (E/32, B/32), block (32,8)
// ---------------------------------------------------------------------------
__global__ __launch_bounds__(256)
void transpose_init_kernel(const float* __restrict__ x,
                           const float* __restrict__ b3) {
    __shared__ float tile[32][33];
    const int e0 = blockIdx.x * 32;
    const int b0 = blockIdx.y * 32;
    const int tx = threadIdx.x, ty = threadIdx.y;

#pragma unroll
    for (int k = 0; k < 4; k++) {
        int b = b0 + ty + k * 8;
        tile[ty + k * 8][tx] = x[(size_t)b * E_ + e0 + tx];   // tile[b_loc][e_loc]
    }
    __syncthreads();
#pragma unroll
    for (int k = 0; k < 4; k++) {
        int e = e0 + ty + k * 8;
        float v = tile[tx][ty + k * 8];                       // b_loc = tx
        size_t idx = (size_t)e * B_ + b0 + tx;
        g_xT[idx] = v;
        g_outT[idx] = v + b3[e];
    }
}

// ---------------------------------------------------------------------------
// Kernel D: tiled transpose outT[e][b] -> out[b][e]
// ---------------------------------------------------------------------------
__global__ __launch_bounds__(256)
void transpose_out_kernel(float* __restrict__ out) {
    __shared__ float tile[32][33];
    const int e0 = blockIdx.x * 32;
    const int b0 = blockIdx.y * 32;
    const int tx = threadIdx.x, ty = threadIdx.y;

#pragma unroll
    for (int k = 0; k < 4; k++) {
        int e = e0 + ty + k * 8;
        tile[ty + k * 8][tx] = g_outT[(size_t)e * B_ + b0 + tx]; // tile[e_loc][b_loc]
    }
    __syncthreads();
#pragma unroll
    for (int k = 0; k < 4; k++) {
        int b = b0 + ty + k * 8;
        out[(size_t)b * E_ + e0 + tx] = tile[tx][ty + k * 8];    // e_loc = tx
    }
}

__device__ __forceinline__ float elu1(float z) {
    return z > 0.0f ? z : expm1f(z);
}

// ---------------------------------------------------------------------------
// Kernel C: one block per function node f, one thread per batch b (128).
// All E-indexed accesses now coalesced via transposed layout.
// ---------------------------------------------------------------------------
__global__ __launch_bounds__(B_)
void fn_node_kernel(const float* __restrict__ s,
                    const float* __restrict__ w1,
                    const float* __restrict__ b1,
                    const float* __restrict__ w2,
                    const float* __restrict__ b2,
                    const float* __restrict__ w3,
                    const int*   __restrict__ src1,   // in_e[f,d] = src1[(f*10+d)*8]
                    const int*   __restrict__ dst3,   // out_e[f,d] = dst3[(f*10+d)*8]
                    const float* __restrict__ g1,
                    const float* __restrict__ bt1,
                    const float* __restrict__ g2,
                    const float* __restrict__ bt2) {
    __shared__ float w1s[DIN_ * C_];
    __shared__ float w2s[C_ * C_];
    __shared__ float w3s[DOUT_ * C_];
    __shared__ int   ine[DIN_];
    __shared__ int   oute[DOUT_];
    __shared__ float b1s[C_], b2s[C_], g1s[C_], bt1s[C_], g2s[C_], bt2s[C_];

    const int f   = blockIdx.x;
    const int tid = threadIdx.x;   // == batch index b

    if (tid < DIN_ * C_)  w1s[tid] = w1[f * (DIN_ * C_) + tid];
    if (tid < C_ * C_)    w2s[tid] = w2[f * (C_ * C_) + tid];
    if (tid < DOUT_ * C_) w3s[tid] = w3[f * (DOUT_ * C_) + tid];
    if (tid < DIN_)       ine[tid]  = src1[(f * DIN_ + tid) * C_];
    if (tid < DOUT_)      oute[tid] = dst3[(f * DOUT_ + tid) * C_];
    if (tid < C_) {
        int hc = f * C_ + tid;
        b1s[tid]  = b1[hc];
        b2s[tid]  = b2[hc];
        g1s[tid]  = g1[hc];
        bt1s[tid] = bt1[hc];
        g2s[tid]  = g2[hc];
        bt2s[tid] = bt2[hc];
    }
    __syncthreads();

    const int b = tid;

    // ---- gather from transposed x: fully coalesced (1 wavefront per load) ----
    float xv[DIN_];
#pragma unroll
    for (int d = 0; d < DIN_; d++) xv[d] = __ldg(&g_xT[(size_t)ine[d] * B_ + b]);

    // ---- w1: 10x8 dense ----
    float h[C_];
#pragma unroll
    for (int c = 0; c < C_; c++) {
        float acc = b1s[c];
#pragma unroll
        for (int d = 0; d < DIN_; d++) acc = fmaf(xv[d], w1s[d * C_ + c], acc);
        h[c] = acc;
    }

    // ---- s[b, f*8 .. f*8+7]: one 32B sector per thread, fully used ----
    const float4* srow = reinterpret_cast<const float4*>(s + (size_t)b * H_ + f * C_);
    float4 sa = srow[0], sb = srow[1];
    float sv[C_] = {sa.x, sa.y, sa.z, sa.w, sb.x, sb.y, sb.z, sb.w};

    // ---- groupLN 1 + affine + elu(s*h) ----
    {
        float sum = 0.f, sq = 0.f;
#pragma unroll
        for (int c = 0; c < C_; c++) { sum += h[c]; sq += h[c] * h[c]; }
        float mu  = sum * 0.125f;
        float var = sq * 0.125f - mu * mu;
        float inv = rsqrtf(var + EPS_);
#pragma unroll
        for (int c = 0; c < C_; c++) {
            float z = (g1s[c] * ((h[c] - mu) * inv) + bt1s[c]) * sv[c];
            h[c] = elu1(z);
        }
    }

    // ---- w2: 8x8 dense block ----
    float h2[C_];
#pragma unroll
    for (int c2 = 0; c2 < C_; c2++) {
        float acc = b2s[c2];
#pragma unroll
        for (int c = 0; c < C_; c++) acc = fmaf(h[c], w2s[c * C_ + c2], acc);
        h2[c2] = acc;
    }

    // ---- groupLN 2 + affine + elu(h*s) ----
    {
        float sum = 0.f, sq = 0.f;
#pragma unroll
        for (int c = 0; c < C_; c++) { sum += h2[c]; sq += h2[c] * h2[c]; }
        float mu  = sum * 0.125f;
        float var = sq * 0.125f - mu * mu;
        float inv = rsqrtf(var + EPS_);
#pragma unroll
        for (int c = 0; c < C_; c++) {
            float z = (g2s[c] * ((h2[c] - mu) * inv) + bt2s[c]) * sv[c];
            h[c] = elu1(z);
        }
    }

    // ---- w3: 8 -> 10 scatter, coalesced atomics into transposed out ----
#pragma unroll
    for (int d = 0; d < DOUT_; d++) {
        float acc = 0.f;
#pragma unroll
        for (int c = 0; c < C_; c++) acc = fmaf(h[c], w3s[d * C_ + c], acc);
        atomicAdd(&g_outT[(size_t)oute[d] * B_ + b], acc);
    }
}

// ---------------------------------------------------------------------------
// Launch
// ---------------------------------------------------------------------------
extern "C" void kernel_launch(void* const* d_in, const int* in_sizes, int n_in,
                              void* d_out, int out_size) {
    const float* x   = (const float*)d_in[0];
    const float* s   = (const float*)d_in[1];
    const float* w1  = (const float*)d_in[2];
    const float* b1  = (const float*)d_in[3];
    const float* w2  = (const float*)d_in[4];
    const float* b2  = (const float*)d_in[5];
    const float* w3  = (const float*)d_in[6];
    const float* b3  = (const float*)d_in[7];
    const float* g1  = (const float*)d_in[8];
    const float* bt1 = (const float*)d_in[9];
    const float* g2  = (const float*)d_in[10];
    const float* bt2 = (const float*)d_in[11];
    const int*   src1 = (const int*)d_in[12];
    const int*   dst3 = (const int*)d_in[17];
    float* out = (float*)d_out;

    dim3 tgrid(E_ / 32, B_ / 32);
    dim3 tblk(32, 8);

    transpose_init_kernel<<<tgrid, tblk>>>(x, b3);
    fn_node_kernel<<<F_, B_>>>(s, w1, b1, w2, b2, w3,
                               src1, dst3, g1, bt1, g2, bt2);
    transpose_out_kernel<<<tgrid, tblk>>>(out);
}